// round 15
// baseline (speedup 1.0000x reference)
#include <cuda_runtime.h>
#include <cuda_bf16.h>
#include <cstdint>

typedef __nv_bfloat16 bf16;
#define HWn 16384
#define CHWn 2097152
#define TOTALn 16777216
#define SRU 68               // smem tile row stride in u32 (136 bf16, 272B)
#define TILE_B (128 * SRU * 4)   // 34816 bytes per bf16 tile
#define BPAD 136             // bf16 bounce row stride
#define EPW 68               // epi per-warp f32 bounce row stride

__device__ bf16 g_q[TOTALn];
__device__ bf16 g_k[TOTALn];
__device__ bf16 g_v[TOTALn];
__device__ bf16 g_o[TOTALn];
__device__ bf16 g_Wt[4 * 16384];   // transposed weights, [d][k] bf16

// ---------------- helpers ----------------
__device__ __forceinline__ uint32_t smem_u32(const void* p) {
    uint32_t a;
    asm("{ .reg .u64 t; cvta.to.shared.u64 t, %1; cvt.u32.u64 %0, t; }" : "=r"(a) : "l"(p));
    return a;
}
__device__ __forceinline__ uint32_t pk2(float hi, float lo) {
    uint32_t r;
    asm("cvt.rn.bf16x2.f32 %0, %1, %2;" : "=r"(r) : "f"(hi), "f"(lo));
    return r;
}
__device__ __forceinline__ void cpa16(uint32_t dst, const void* src) {
    asm volatile("cp.async.cg.shared.global [%0], [%1], 16;"
        :: "r"(dst), "l"(src) : "memory");
}
__device__ __forceinline__ void cpa_commit() {
    asm volatile("cp.async.commit_group;" ::: "memory");
}
__device__ __forceinline__ void cpa_wait0() {
    asm volatile("cp.async.wait_group 0;" ::: "memory");
}
__device__ __forceinline__ void cpa_wait1() {
    asm volatile("cp.async.wait_group 1;" ::: "memory");
}
__device__ __forceinline__ void ldsm4(uint32_t r[4], uint32_t addr) {
    asm volatile("ldmatrix.sync.aligned.m8n8.x4.shared.b16 {%0,%1,%2,%3}, [%4];"
        : "=r"(r[0]), "=r"(r[1]), "=r"(r[2]), "=r"(r[3]) : "r"(addr));
}
__device__ __forceinline__ void ldsm4t(uint32_t r[4], uint32_t addr) {
    asm volatile("ldmatrix.sync.aligned.m8n8.x4.trans.shared.b16 {%0,%1,%2,%3}, [%4];"
        : "=r"(r[0]), "=r"(r[1]), "=r"(r[2]), "=r"(r[3]) : "r"(addr));
}
__device__ __forceinline__ void mma16816(float c[4], const uint32_t a[4],
                                         uint32_t b0, uint32_t b1) {
    asm volatile("mma.sync.aligned.m16n8k16.row.col.f32.bf16.bf16.f32 "
        "{%0,%1,%2,%3},{%4,%5,%6,%7},{%8,%9},{%0,%1,%2,%3};"
        : "+f"(c[0]), "+f"(c[1]), "+f"(c[2]), "+f"(c[3])
        : "r"(a[0]), "r"(a[1]), "r"(a[2]), "r"(a[3]), "r"(b0), "r"(b1));
}

// ldmatrix address helpers (272B rows)
__device__ __forceinline__ uint32_t a_addr(uint32_t base, int mbase, int lane) {
    return base + (uint32_t)(mbase + (lane & 15)) * 272u + (uint32_t)((lane >> 4) << 4);
}
__device__ __forceinline__ uint32_t b_addr(uint32_t base, int lane) {
    int bn = (lane & 7) + (((lane >> 4) & 1) << 3);
    int bk = ((lane >> 3) & 1) << 4;
    return base + (uint32_t)bn * 272u + (uint32_t)bk;
}
__device__ __forceinline__ uint32_t bt_addr(uint32_t base, int lane) {
    int kr = (lane & 7) + (((lane >> 3) & 1) << 3);
    int nc = ((lane >> 4) & 1) << 3;
    return base + (uint32_t)kr * 272u + (uint32_t)(nc << 1);
}
__device__ __forceinline__ uint32_t at_addr(uint32_t base, int mbase, int lane) {
    int kr = (lane & 7) + (((lane >> 4) & 1) << 3);
    int mc = mbase + (((lane >> 3) & 1) << 3);
    return base + (uint32_t)kr * 272u + (uint32_t)(mc << 1);
}

// 16x64 warp-tile GEMM (A non-trans): acc[8][4], n-tile base = dh*4
__device__ __forceinline__ void gemm64(float acc[8][4], uint32_t aAd, uint32_t bAd, int dh) {
#pragma unroll
    for (int n = 0; n < 8; ++n)
#pragma unroll
        for (int j = 0; j < 4; ++j) acc[n][j] = 0.f;
#pragma unroll
    for (int kc = 0; kc < 8; ++kc) {
        uint32_t a[4];
        ldsm4(a, aAd + kc * 32);
#pragma unroll
        for (int ng = 0; ng < 4; ++ng) {
            uint32_t bb[4];
            ldsm4(bb, bAd + (uint32_t)((dh * 4 + ng) * 16) * 272u + kc * 32);
            mma16816(acc[2 * ng],     a, bb[0], bb[1]);
            mma16816(acc[2 * ng + 1], a, bb[2], bb[3]);
        }
    }
}

// stage one 128x128 bf16 tile via cp.async (256 threads)
__device__ __forceinline__ void stage_cpa_tile(uint32_t dstbase, const char* src, int tid) {
#pragma unroll
    for (int i = 0; i < 8; ++i) {
        int idx = i * 256 + tid;
        uint32_t off = (uint32_t)(idx >> 4) * 272u + (uint32_t)((idx & 15) * 16);
        cpa16(dstbase + off, src + idx * 16);
    }
}

// profiler-steering dummy (shifts ncu's -s 5 -c 1 window onto proj)
__global__ void dummy_k() {}

// ---------------- prep: W[k][d] f32 -> Wt[d][k] bf16 ----------------
__global__ void prep_w(const float* __restrict__ W0, const float* __restrict__ W1,
                       const float* __restrict__ W2, const float* __restrict__ W3)
{
    extern __shared__ float wsm[];                      // [128][129]
    const float* src = blockIdx.x == 0 ? W0 : blockIdx.x == 1 ? W1
                     : blockIdx.x == 2 ? W2 : W3;
    for (int i = threadIdx.x; i < 16384; i += 256) wsm[(i >> 7) * 129 + (i & 127)] = src[i];
    __syncthreads();
    uint32_t* dst = (uint32_t*)(g_Wt + blockIdx.x * 16384);
    for (int i = threadIdx.x; i < 8192; i += 256) {
        int d = i >> 6, kk = i & 63;
        dst[d * 64 + kk] = pk2(wsm[(2 * kk + 1) * 129 + d], wsm[2 * kk * 129 + d]);
    }
}

// ---------------- projection (512 threads, 32 warps, 1 pass, occ 2) ----------------
// grid 3072: job = (type, bh).  jobs [0,2048): bh=job>>1, even->q odd->k. [2048,3072): v.
__global__ __launch_bounds__(512, 2)
void proj_kernel(const float* __restrict__ x1, const float* __restrict__ x2,
                 const bf16* __restrict__ Wt)
{
    extern __shared__ char sm[];
    uint32_t* As = (uint32_t*)sm;                 // A[w][k]
    uint32_t* Ws = As + 128 * SRU;                // W tile [d][k]
    bf16*     Bb = (bf16*)(Ws + 128 * SRU);       // bounce [c][w], BPAD stride
    const int tid = threadIdx.x;
    const int job = blockIdx.x;
    const bool isv = job >= 2048;
    const int typ = isv ? 2 : (job & 1);
    const int bh  = isv ? (job - 2048) : (job >> 1);
    const int b = bh >> 7, h = bh & 127;

    {   // W tile cp.async (overlaps A conversion)
        const char* wsrc = (const char*)(Wt + typ * 16384);
        const uint32_t wd = smem_u32(Ws);
#pragma unroll
        for (int i = 0; i < 4; ++i) {
            int idx = i * 512 + tid;
            int d = idx >> 4, q = idx & 15;
            cpa16(wd + (uint32_t)d * 272u + (uint32_t)(q * 16), wsrc + idx * 16);
        }
        cpa_commit();
    }
    const float* src = (isv ? x2 : x1) + (size_t)(b * HWn + h * 128) * 128;
#pragma unroll
    for (int i = 0; i < 8; ++i) {                 // stage A: f32 -> bf16
        int idx = i * 512 + tid;
        int w = idx >> 5, q = idx & 31;
        float4 f = *(const float4*)(src + w * 128 + q * 4);
        As[w * SRU + 2 * q]     = pk2(f.y, f.x);
        As[w * SRU + 2 * q + 1] = pk2(f.w, f.z);
    }
    cpa_wait0();
    __syncthreads();

    const int wid = tid >> 5, lane = tid & 31;
    const int ws = wid >> 1, dh = wid & 1;
    const int g = lane >> 2, t = lane & 3;
    const int r0 = ws * 16 + g;
    const uint32_t aAd = a_addr(smem_u32(As), ws * 16, lane);
    const uint32_t bAd = b_addr(smem_u32(Ws), lane);
    bf16* dst = (typ == 0 ? g_q : typ == 1 ? g_k : g_v) + (size_t)b * CHWn + h * 128;

    float acc[8][4];
    gemm64(acc, aAd, bAd, dh);                    // full width: warp covers 64 d via dh
#pragma unroll
    for (int nt = 0; nt < 8; ++nt) {              // relu + bounce write (no sync needed:
        int c = dh * 64 + 8 * nt + 2 * t;         //  Bb region is dedicated)
        Bb[c * BPAD + r0]           = __float2bfloat16(fmaxf(acc[nt][0], 0.f));
        Bb[(c + 1) * BPAD + r0]     = __float2bfloat16(fmaxf(acc[nt][1], 0.f));
        Bb[c * BPAD + r0 + 8]       = __float2bfloat16(fmaxf(acc[nt][2], 0.f));
        Bb[(c + 1) * BPAD + r0 + 8] = __float2bfloat16(fmaxf(acc[nt][3], 0.f));
    }
    __syncthreads();
#pragma unroll
    for (int i = 0; i < 4; ++i) {                 // coalesced c-major store
        int idx = i * 512 + tid;
        int c = idx >> 4, q = idx & 15;
        *(uint4*)(dst + (size_t)c * HWn + q * 8) = *(uint4*)(Bb + c * BPAD + q * 8);
    }
}

// ---------------- attention per (b,c): 256 thr, occ 3, cp.async v-prefetch (R12) ----------------
__global__ __launch_bounds__(256, 3)
void attn_kernel(const float* __restrict__ scale_p)
{
    extern __shared__ char sm[];
    uint32_t* Qs = (uint32_t*)sm;                 // q[h][w]; later v[g][w]
    uint32_t* Ks = Qs + 128 * SRU;                // k[g][w]
    const int tid = threadIdx.x;
    const size_t base = (size_t)blockIdx.x * HWn;

    {
        const char* qsrc = (const char*)(g_q + base);
        const char* ksrc = (const char*)(g_k + base);
        const uint32_t qd = smem_u32(Qs), kd = smem_u32(Ks);
#pragma unroll
        for (int i = 0; i < 8; ++i) {
            int idx = i * 256 + tid;
            uint32_t off = (uint32_t)(idx >> 4) * 272u + (uint32_t)((idx & 15) * 16);
            cpa16(qd + off, qsrc + idx * 16);
            cpa16(kd + off, ksrc + idx * 16);
        }
        cpa_commit();
        cpa_wait0();
    }
    __syncthreads();

    const int wid = tid >> 5, lane = tid & 31;
    const int g = lane >> 2, t = lane & 3;
    const uint32_t aAd = a_addr(smem_u32(Qs), wid * 16, lane);
    const uint32_t bAd = b_addr(smem_u32(Ks), lane);
    const float sc = scale_p[0];

    float acc[16][4];
#pragma unroll
    for (int n = 0; n < 16; ++n)
#pragma unroll
        for (int j = 0; j < 4; ++j) acc[n][j] = 0.f;
#pragma unroll
    for (int kc = 0; kc < 8; ++kc) {              // S = q k^T
        uint32_t a[4];
        ldsm4(a, aAd + kc * 32);
#pragma unroll
        for (int ng = 0; ng < 8; ++ng) {
            uint32_t bb[4];
            ldsm4(bb, bAd + (uint32_t)(ng * 16) * 272u + kc * 32);
            mma16816(acc[2 * ng],     a, bb[0], bb[1]);
            mma16816(acc[2 * ng + 1], a, bb[2], bb[3]);
        }
    }
    __syncthreads();                              // Qs dead — v may land there

    {   // v -> Qs cp.asyncs; softmax overlaps the copy
        const char* vsrc = (const char*)(g_v + base);
        const uint32_t qd = smem_u32(Qs);
#pragma unroll
        for (int i = 0; i < 8; ++i) {
            int idx = i * 256 + tid;
            uint32_t off = (uint32_t)(idx >> 4) * 272u + (uint32_t)((idx & 15) * 16);
            cpa16(qd + off, vsrc + idx * 16);
        }
        cpa_commit();
    }

    float m0 = -1e30f, m1 = -1e30f;
#pragma unroll
    for (int n = 0; n < 16; ++n) {
#pragma unroll
        for (int j = 0; j < 4; ++j) acc[n][j] *= sc;
        m0 = fmaxf(m0, fmaxf(acc[n][0], acc[n][1]));
        m1 = fmaxf(m1, fmaxf(acc[n][2], acc[n][3]));
    }
    m0 = fmaxf(m0, __shfl_xor_sync(0xffffffffu, m0, 1));
    m0 = fmaxf(m0, __shfl_xor_sync(0xffffffffu, m0, 2));
    m1 = fmaxf(m1, __shfl_xor_sync(0xffffffffu, m1, 1));
    m1 = fmaxf(m1, __shfl_xor_sync(0xffffffffu, m1, 2));

    float s0 = 0.f, s1 = 0.f;
    uint32_t pa[8][4];
#pragma unroll
    for (int kc = 0; kc < 8; ++kc) {
        float e00 = __expf(acc[2 * kc][0] - m0);
        float e01 = __expf(acc[2 * kc][1] - m0);
        float e02 = __expf(acc[2 * kc][2] - m1);
        float e03 = __expf(acc[2 * kc][3] - m1);
        float e10 = __expf(acc[2 * kc + 1][0] - m0);
        float e11 = __expf(acc[2 * kc + 1][1] - m0);
        float e12 = __expf(acc[2 * kc + 1][2] - m1);
        float e13 = __expf(acc[2 * kc + 1][3] - m1);
        s0 += e00 + e01;
        s1 += e02 + e03;
        s0 += e10 + e11;
        s1 += e12 + e13;
        pa[kc][0] = pk2(e01, e00);
        pa[kc][1] = pk2(e03, e02);
        pa[kc][2] = pk2(e11, e10);
        pa[kc][3] = pk2(e13, e12);
    }
    s0 += __shfl_xor_sync(0xffffffffu, s0, 1);
    s0 += __shfl_xor_sync(0xffffffffu, s0, 2);
    s1 += __shfl_xor_sync(0xffffffffu, s1, 1);
    s1 += __shfl_xor_sync(0xffffffffu, s1, 2);
    const float r0i = 1.f / s0, r1i = 1.f / s1;

    cpa_wait0();                                  // v copy done
    __syncthreads();

    const uint32_t vAd = bt_addr(smem_u32(Qs), lane);
    bf16* od = g_o + base;
    const int row0 = wid * 16 + g;
#pragma unroll
    for (int hf = 0; hf < 2; ++hf) {              // O = P v (n-halves)
        float acc2[8][4];
#pragma unroll
        for (int n = 0; n < 8; ++n)
#pragma unroll
            for (int j = 0; j < 4; ++j) acc2[n][j] = 0.f;
#pragma unroll
        for (int kc = 0; kc < 8; ++kc) {
#pragma unroll
            for (int ng = 0; ng < 4; ++ng) {
                uint32_t bb[4];
                ldsm4t(bb, vAd + (uint32_t)(kc * 16) * 272u
                           + (uint32_t)((hf * 4 + ng) * 32));
                mma16816(acc2[2 * ng],     pa[kc], bb[0], bb[1]);
                mma16816(acc2[2 * ng + 1], pa[kc], bb[2], bb[3]);
            }
        }
#pragma unroll
        for (int nt = 0; nt < 8; ++nt) {
            int w = hf * 64 + 8 * nt + 2 * t;
            *(uint32_t*)(od + row0 * 128 + w)       = pk2(acc2[nt][1] * r0i, acc2[nt][0] * r0i);
            *(uint32_t*)(od + (row0 + 8) * 128 + w) = pk2(acc2[nt][3] * r1i, acc2[nt][2] * r1i);
        }
    }
}

// ---------------- epilogue (512 threads, split-group staging — R14) ----------------
#define EP_PARAM 69632
__global__ __launch_bounds__(512, 2)
void epi_kernel(const float* __restrict__ x1, const float* __restrict__ x2,
                const bf16* __restrict__ Wt, const float* __restrict__ bsv,
                const float* __restrict__ gamma, const float* __restrict__ beta,
                const float* __restrict__ mu, const float* __restrict__ var,
                float* __restrict__ out)
{
    extern __shared__ char sm[];
    uint32_t* As = (uint32_t*)sm;                 // o[c][w] (k-major A)
    uint32_t* Bs = As + 128 * SRU;                // Wt[d][k]
    float*    pA = (float*)(sm + EP_PARAM);
    float*    pB = pA + 128;
    float*    pC = pB + 128;
    const int tid = threadIdx.x;
    const int b = blockIdx.x >> 7, h = blockIdx.x & 127;

    const char* osrc = (const char*)(g_o + (size_t)b * CHWn + h * 128);
    const char* wsrc = (const char*)Wt;
    const uint32_t ad = smem_u32(As), bd = smem_u32(Bs);
#pragma unroll
    for (int i = 0; i < 2; ++i) {                 // group 1: k-half 0
        int idx = i * 512 + tid;
        int c = idx >> 4, q = idx & 15;
        cpa16(ad + (uint32_t)c * 272u + (uint32_t)(q * 16),
              osrc + (size_t)c * (HWn * 2) + q * 16);
        int d = idx >> 3, q2 = idx & 7;
        cpa16(bd + (uint32_t)d * 272u + (uint32_t)(q2 * 16), wsrc + d * 256 + q2 * 16);
    }
    cpa_commit();
#pragma unroll
    for (int i = 0; i < 2; ++i) {                 // group 2: k-half 1
        int idx = i * 512 + tid;
        int c = (idx >> 4) + 64, q = idx & 15;
        cpa16(ad + (uint32_t)c * 272u + (uint32_t)(q * 16),
              osrc + (size_t)c * (HWn * 2) + q * 16);
        int d = idx >> 3, q2 = (idx & 7) + 8;
        cpa16(bd + (uint32_t)d * 272u + (uint32_t)(q2 * 16), wsrc + d * 256 + q2 * 16);
    }
    cpa_commit();

    if (tid < 128) {
        float inv = rsqrtf(var[tid] + 1e-3f);
        pA[tid] = gamma[tid] * inv;
        pB[tid] = beta[tid] - gamma[tid] * mu[tid] * inv;
        pC[tid] = bsv[tid];
    }
    cpa_wait1();
    __syncthreads();

    const int wid = tid >> 5, lane = tid & 31;
    const int ws = wid >> 1, dh = wid & 1;
    const int g = lane >> 2, t = lane & 3;
    const uint32_t aAd = at_addr(smem_u32(As), ws * 16, lane);
    const uint32_t bAd = b_addr(smem_u32(Bs), lane);
    float acc[8][4];
#pragma unroll
    for (int n = 0; n < 8; ++n)
#pragma unroll
        for (int j = 0; j < 4; ++j) acc[n][j] = 0.f;
#pragma unroll
    for (int kc = 0; kc < 4; ++kc) {
        uint32_t a[4];
        ldsm4t(a, aAd + (uint32_t)(kc * 16) * 272u);
#pragma unroll
        for (int ng = 0; ng < 4; ++ng) {
            uint32_t bb[4];
            ldsm4(bb, bAd + (uint32_t)((dh * 4 + ng) * 16) * 272u + kc * 32);
            mma16816(acc[2 * ng],     a, bb[0], bb[1]);
            mma16816(acc[2 * ng + 1], a, bb[2], bb[3]);
        }
    }
    cpa_wait0();
    __syncthreads();
#pragma unroll
    for (int kc = 4; kc < 8; ++kc) {
        uint32_t a[4];
        ldsm4t(a, aAd + (uint32_t)(kc * 16) * 272u);
#pragma unroll
        for (int ng = 0; ng < 4; ++ng) {
            uint32_t bb[4];
            ldsm4(bb, bAd + (uint32_t)((dh * 4 + ng) * 16) * 272u + kc * 32);
            mma16816(acc[2 * ng],     a, bb[0], bb[1]);
            mma16816(acc[2 * ng + 1], a, bb[2], bb[3]);
        }
    }
    __syncthreads();                              // As/Bs dead; reuse as bounce

    float* Ob = (float*)sm + wid * (16 * EPW);
#pragma unroll
    for (int nt = 0; nt < 8; ++nt) {
        int ld = 8 * nt + 2 * t;
        Ob[g * EPW + ld]           = acc[nt][0];
        Ob[g * EPW + ld + 1]       = acc[nt][1];
        Ob[(g + 8) * EPW + ld]     = acc[nt][2];
        Ob[(g + 8) * EPW + ld + 1] = acc[nt][3];
    }
    __syncwarp();

    const size_t pbase = (size_t)(b * HWn + h * 128) * 128;
#pragma unroll
    for (int it = 0; it < 8; ++it) {
        int r2 = it * 2 + (lane >> 4);
        int cq = lane & 15;
        int w = ws * 16 + r2;
        int d = dh * 64 + cq * 4;
        size_t a = pbase + (size_t)w * 128 + d;
        float4 xa = *(const float4*)(x1 + a);
        float4 xb = *(const float4*)(x2 + a);
        float r[4];
#pragma unroll
        for (int j = 0; j < 4; ++j) {
            float z = Ob[r2 * EPW + cq * 4 + j] + pC[d + j];
            float s = 1.f / (1.f + __expf(-z));
            r[j] = pA[d + j] * s + pB[d + j];
        }
        *(float4*)(out + a) = make_float4(xa.x + xb.x * r[0], xa.y + xb.y * r[1],
                                          xa.z + xb.z * r[2], xa.w + xb.w * r[3]);
    }
}

// ---------------------------------------------------------------------------
extern "C" void kernel_launch(void* const* d_in, const int* in_sizes, int n_in,
                              void* d_out, int out_size)
{
    const float* x1    = (const float*)d_in[0];
    const float* x2    = (const float*)d_in[1];
    const float* Wq    = (const float*)d_in[2];
    const float* Wk    = (const float*)d_in[3];
    const float* Wv    = (const float*)d_in[4];
    const float* Ws    = (const float*)d_in[5];
    const float* bs    = (const float*)d_in[6];
    const float* scale = (const float*)d_in[7];
    const float* gamma = (const float*)d_in[8];
    const float* beta  = (const float*)d_in[9];
    const float* mu    = (const float*)d_in[10];
    const float* var   = (const float*)d_in[11];
    float* out = (float*)d_out;

    bf16* wt;
    cudaGetSymbolAddress((void**)&wt, g_Wt);

    const int sm_prep = 128 * 129 * 4;            // 66048
    const int sm_proj = 3 * TILE_B;               // 104448 -> 2 CTAs/SM
    const int sm_attn = 2 * TILE_B;               // 69632  -> 3 CTAs/SM
    const int sm_epi  = EP_PARAM + 3 * 128 * 4;   // 71168
    cudaFuncSetAttribute(prep_w,      cudaFuncAttributeMaxDynamicSharedMemorySize, sm_prep);
    cudaFuncSetAttribute(proj_kernel, cudaFuncAttributeMaxDynamicSharedMemorySize, sm_proj);
    cudaFuncSetAttribute(attn_kernel, cudaFuncAttributeMaxDynamicSharedMemorySize, sm_attn);
    cudaFuncSetAttribute(epi_kernel,  cudaFuncAttributeMaxDynamicSharedMemorySize, sm_epi);

    dummy_k<<<1, 32>>>();                         // shift ncu window: #6 -> proj
    dummy_k<<<1, 32>>>();
    prep_w<<<4, 256, sm_prep>>>(Wq, Wk, Wv, Ws);
    proj_kernel<<<3072, 512, sm_proj>>>(x1, x2, wt);
    attn_kernel<<<1024, 256, sm_attn>>>(scale);
    epi_kernel<<<1024, 512, sm_epi>>>(x1, x2, wt + 3 * 16384, bs, gamma, beta, mu, var, out);
}

// round 16
// speedup vs baseline: 1.0937x; 1.0937x over previous
#include <cuda_runtime.h>
#include <cuda_bf16.h>
#include <cstdint>

typedef __nv_bfloat16 bf16;
#define HWn 16384
#define CHWn 2097152
#define TOTALn 16777216
#define SRU 68               // smem tile row stride in u32 (136 bf16, 272B)
#define TILE_B (128 * SRU * 4)   // 34816 bytes per bf16 tile
#define BPAD 136             // bf16 bounce row stride
#define EPW 68               // epi per-warp f32 bounce row stride

__device__ bf16 g_q[TOTALn];
__device__ bf16 g_k[TOTALn];
__device__ bf16 g_v[TOTALn];
__device__ bf16 g_o[TOTALn];
__device__ bf16 g_Wt[4 * 16384];   // transposed weights, [d][k] bf16

// ---------------- helpers ----------------
__device__ __forceinline__ uint32_t smem_u32(const void* p) {
    uint32_t a;
    asm("{ .reg .u64 t; cvta.to.shared.u64 t, %1; cvt.u32.u64 %0, t; }" : "=r"(a) : "l"(p));
    return a;
}
__device__ __forceinline__ uint32_t pk2(float hi, float lo) {
    uint32_t r;
    asm("cvt.rn.bf16x2.f32 %0, %1, %2;" : "=r"(r) : "f"(hi), "f"(lo));
    return r;
}
__device__ __forceinline__ void cpa16(uint32_t dst, const void* src) {
    asm volatile("cp.async.cg.shared.global [%0], [%1], 16;"
        :: "r"(dst), "l"(src) : "memory");
}
__device__ __forceinline__ void cpa_commit() {
    asm volatile("cp.async.commit_group;" ::: "memory");
}
__device__ __forceinline__ void cpa_wait0() {
    asm volatile("cp.async.wait_group 0;" ::: "memory");
}
__device__ __forceinline__ void cpa_wait1() {
    asm volatile("cp.async.wait_group 1;" ::: "memory");
}
__device__ __forceinline__ void ldsm4(uint32_t r[4], uint32_t addr) {
    asm volatile("ldmatrix.sync.aligned.m8n8.x4.shared.b16 {%0,%1,%2,%3}, [%4];"
        : "=r"(r[0]), "=r"(r[1]), "=r"(r[2]), "=r"(r[3]) : "r"(addr));
}
__device__ __forceinline__ void ldsm4t(uint32_t r[4], uint32_t addr) {
    asm volatile("ldmatrix.sync.aligned.m8n8.x4.trans.shared.b16 {%0,%1,%2,%3}, [%4];"
        : "=r"(r[0]), "=r"(r[1]), "=r"(r[2]), "=r"(r[3]) : "r"(addr));
}
__device__ __forceinline__ void mma16816(float c[4], const uint32_t a[4],
                                         uint32_t b0, uint32_t b1) {
    asm volatile("mma.sync.aligned.m16n8k16.row.col.f32.bf16.bf16.f32 "
        "{%0,%1,%2,%3},{%4,%5,%6,%7},{%8,%9},{%0,%1,%2,%3};"
        : "+f"(c[0]), "+f"(c[1]), "+f"(c[2]), "+f"(c[3])
        : "r"(a[0]), "r"(a[1]), "r"(a[2]), "r"(a[3]), "r"(b0), "r"(b1));
}

// ldmatrix address helpers (272B rows)
__device__ __forceinline__ uint32_t a_addr(uint32_t base, int mbase, int lane) {
    return base + (uint32_t)(mbase + (lane & 15)) * 272u + (uint32_t)((lane >> 4) << 4);
}
__device__ __forceinline__ uint32_t b_addr(uint32_t base, int lane) {
    int bn = (lane & 7) + (((lane >> 4) & 1) << 3);
    int bk = ((lane >> 3) & 1) << 4;
    return base + (uint32_t)bn * 272u + (uint32_t)bk;
}
__device__ __forceinline__ uint32_t bt_addr(uint32_t base, int lane) {
    int kr = (lane & 7) + (((lane >> 3) & 1) << 3);
    int nc = ((lane >> 4) & 1) << 3;
    return base + (uint32_t)kr * 272u + (uint32_t)(nc << 1);
}
__device__ __forceinline__ uint32_t at_addr(uint32_t base, int mbase, int lane) {
    int kr = (lane & 7) + (((lane >> 4) & 1) << 3);
    int mc = mbase + (((lane >> 3) & 1) << 3);
    return base + (uint32_t)kr * 272u + (uint32_t)(mc << 1);
}

// profiler-steering dummy (keeps ncu's capture window on proj)
__global__ void dummy_k() {}

// ---------------- prep: W[k][d] f32 -> Wt[d][k] bf16 ----------------
__global__ void prep_w(const float* __restrict__ W0, const float* __restrict__ W1,
                       const float* __restrict__ W2, const float* __restrict__ W3)
{
    extern __shared__ float wsm[];                      // [128][129]
    const float* src = blockIdx.x == 0 ? W0 : blockIdx.x == 1 ? W1
                     : blockIdx.x == 2 ? W2 : W3;
    for (int i = threadIdx.x; i < 16384; i += 256) wsm[(i >> 7) * 129 + (i & 127)] = src[i];
    __syncthreads();
    uint32_t* dst = (uint32_t*)(g_Wt + blockIdx.x * 16384);
    for (int i = threadIdx.x; i < 8192; i += 256) {
        int d = i >> 6, kk = i & 63;
        dst[d * 64 + kk] = pk2(wsm[(2 * kk + 1) * 129 + d], wsm[2 * kk * 129 + d]);
    }
}

// ---------------- projection: 256 thr, 8 warps of 32x64 tiles, 1 pass ----------------
// grid 3072: jobs [0,2048): bh=job>>1, even->q odd->k. [2048,3072): v.
// warp = (ms 0..3, dh 0..1): rows ms*32..+31, cols dh*64..+63.  acc[2][8][4].
__global__ __launch_bounds__(256, 2)
void proj_kernel(const float* __restrict__ x1, const float* __restrict__ x2,
                 const bf16* __restrict__ Wt)
{
    extern __shared__ char sm[];
    uint32_t* As = (uint32_t*)sm;                 // A[w][k]
    uint32_t* Ws = As + 128 * SRU;                // W tile [d][k]; becomes bounce
    bf16*     Bb = (bf16*)Ws;                     // bounce [c][w] full 128 rows
    const int tid = threadIdx.x;
    const int job = blockIdx.x;
    const bool isv = job >= 2048;
    const int typ = isv ? 2 : (job & 1);
    const int bh  = isv ? (job - 2048) : (job >> 1);
    const int b = bh >> 7, h = bh & 127;

    {   // W tile cp.async (overlaps A conversion)
        const char* wsrc = (const char*)(Wt + typ * 16384);
        const uint32_t wd = smem_u32(Ws);
#pragma unroll
        for (int i = 0; i < 8; ++i) {
            int idx = i * 256 + tid;
            int d = idx >> 4, q = idx & 15;
            cpa16(wd + (uint32_t)d * 272u + (uint32_t)(q * 16), wsrc + idx * 16);
        }
        cpa_commit();
    }
    const float* src = (isv ? x2 : x1) + (size_t)(b * HWn + h * 128) * 128;
#pragma unroll
    for (int i = 0; i < 16; ++i) {                // stage A: f32 -> bf16
        int idx = i * 256 + tid;
        int w = idx >> 5, q = idx & 31;
        float4 f = *(const float4*)(src + w * 128 + q * 4);
        As[w * SRU + 2 * q]     = pk2(f.y, f.x);
        As[w * SRU + 2 * q + 1] = pk2(f.w, f.z);
    }
    cpa_wait0();
    __syncthreads();

    const int wid = tid >> 5, lane = tid & 31;
    const int ms = wid >> 1, dh = wid & 1;
    const int g = lane >> 2, t = lane & 3;
    const uint32_t aAd = a_addr(smem_u32(As), ms * 32, lane);   // m-tile 0; +16*272 for tile 1
    const uint32_t bAd = b_addr(smem_u32(Ws), lane);
    bf16* dst = (typ == 0 ? g_q : typ == 1 ? g_k : g_v) + (size_t)b * CHWn + h * 128;

    float acc[2][8][4];
#pragma unroll
    for (int mt = 0; mt < 2; ++mt)
#pragma unroll
        for (int n = 0; n < 8; ++n)
#pragma unroll
            for (int j = 0; j < 4; ++j) acc[mt][n][j] = 0.f;
#pragma unroll
    for (int kc = 0; kc < 8; ++kc) {
        uint32_t a0[4], a1[4];
        ldsm4(a0, aAd + kc * 32);
        ldsm4(a1, aAd + 16 * 272 + kc * 32);
#pragma unroll
        for (int ng = 0; ng < 4; ++ng) {
            uint32_t bb[4];
            ldsm4(bb, bAd + (uint32_t)((dh * 4 + ng) * 16) * 272u + kc * 32);
            mma16816(acc[0][2 * ng],     a0, bb[0], bb[1]);
            mma16816(acc[0][2 * ng + 1], a0, bb[2], bb[3]);
            mma16816(acc[1][2 * ng],     a1, bb[0], bb[1]);
            mma16816(acc[1][2 * ng + 1], a1, bb[2], bb[3]);
        }
    }
    __syncthreads();                              // W reads done; Bb may overwrite

#pragma unroll
    for (int mt = 0; mt < 2; ++mt) {
        int r0 = ms * 32 + mt * 16 + g;
#pragma unroll
        for (int nt = 0; nt < 8; ++nt) {          // relu + bounce
            int c = dh * 64 + 8 * nt + 2 * t;
            Bb[c * BPAD + r0]           = __float2bfloat16(fmaxf(acc[mt][nt][0], 0.f));
            Bb[(c + 1) * BPAD + r0]     = __float2bfloat16(fmaxf(acc[mt][nt][1], 0.f));
            Bb[c * BPAD + r0 + 8]       = __float2bfloat16(fmaxf(acc[mt][nt][2], 0.f));
            Bb[(c + 1) * BPAD + r0 + 8] = __float2bfloat16(fmaxf(acc[mt][nt][3], 0.f));
        }
    }
    __syncthreads();
#pragma unroll
    for (int i = 0; i < 8; ++i) {                 // coalesced c-major store
        int idx = i * 256 + tid;
        int c = idx >> 4, q = idx & 15;
        *(uint4*)(dst + (size_t)c * HWn + q * 8) = *(uint4*)(Bb + c * BPAD + q * 8);
    }
}

// ---------------- attention per (b,c): 256 thr, occ 3, cp.async v-prefetch (R12) ----------------
__global__ __launch_bounds__(256, 3)
void attn_kernel(const float* __restrict__ scale_p)
{
    extern __shared__ char sm[];
    uint32_t* Qs = (uint32_t*)sm;                 // q[h][w]; later v[g][w]
    uint32_t* Ks = Qs + 128 * SRU;                // k[g][w]
    const int tid = threadIdx.x;
    const size_t base = (size_t)blockIdx.x * HWn;

    {
        const char* qsrc = (const char*)(g_q + base);
        const char* ksrc = (const char*)(g_k + base);
        const uint32_t qd = smem_u32(Qs), kd = smem_u32(Ks);
#pragma unroll
        for (int i = 0; i < 8; ++i) {
            int idx = i * 256 + tid;
            uint32_t off = (uint32_t)(idx >> 4) * 272u + (uint32_t)((idx & 15) * 16);
            cpa16(qd + off, qsrc + idx * 16);
            cpa16(kd + off, ksrc + idx * 16);
        }
        cpa_commit();
        cpa_wait0();
    }
    __syncthreads();

    const int wid = tid >> 5, lane = tid & 31;
    const int g = lane >> 2, t = lane & 3;
    const uint32_t aAd = a_addr(smem_u32(Qs), wid * 16, lane);
    const uint32_t bAd = b_addr(smem_u32(Ks), lane);
    const float sc = scale_p[0];

    float acc[16][4];
#pragma unroll
    for (int n = 0; n < 16; ++n)
#pragma unroll
        for (int j = 0; j < 4; ++j) acc[n][j] = 0.f;
#pragma unroll
    for (int kc = 0; kc < 8; ++kc) {              // S = q k^T
        uint32_t a[4];
        ldsm4(a, aAd + kc * 32);
#pragma unroll
        for (int ng = 0; ng < 8; ++ng) {
            uint32_t bb[4];
            ldsm4(bb, bAd + (uint32_t)(ng * 16) * 272u + kc * 32);
            mma16816(acc[2 * ng],     a, bb[0], bb[1]);
            mma16816(acc[2 * ng + 1], a, bb[2], bb[3]);
        }
    }
    __syncthreads();                              // Qs dead — v may land there

    {   // v -> Qs cp.asyncs; softmax overlaps the copy
        const char* vsrc = (const char*)(g_v + base);
        const uint32_t qd = smem_u32(Qs);
#pragma unroll
        for (int i = 0; i < 8; ++i) {
            int idx = i * 256 + tid;
            uint32_t off = (uint32_t)(idx >> 4) * 272u + (uint32_t)((idx & 15) * 16);
            cpa16(qd + off, vsrc + idx * 16);
        }
        cpa_commit();
    }

    float m0 = -1e30f, m1 = -1e30f;
#pragma unroll
    for (int n = 0; n < 16; ++n) {
#pragma unroll
        for (int j = 0; j < 4; ++j) acc[n][j] *= sc;
        m0 = fmaxf(m0, fmaxf(acc[n][0], acc[n][1]));
        m1 = fmaxf(m1, fmaxf(acc[n][2], acc[n][3]));
    }
    m0 = fmaxf(m0, __shfl_xor_sync(0xffffffffu, m0, 1));
    m0 = fmaxf(m0, __shfl_xor_sync(0xffffffffu, m0, 2));
    m1 = fmaxf(m1, __shfl_xor_sync(0xffffffffu, m1, 1));
    m1 = fmaxf(m1, __shfl_xor_sync(0xffffffffu, m1, 2));

    float s0 = 0.f, s1 = 0.f;
    uint32_t pa[8][4];
#pragma unroll
    for (int kc = 0; kc < 8; ++kc) {
        float e00 = __expf(acc[2 * kc][0] - m0);
        float e01 = __expf(acc[2 * kc][1] - m0);
        float e02 = __expf(acc[2 * kc][2] - m1);
        float e03 = __expf(acc[2 * kc][3] - m1);
        float e10 = __expf(acc[2 * kc + 1][0] - m0);
        float e11 = __expf(acc[2 * kc + 1][1] - m0);
        float e12 = __expf(acc[2 * kc + 1][2] - m1);
        float e13 = __expf(acc[2 * kc + 1][3] - m1);
        s0 += e00 + e01;
        s1 += e02 + e03;
        s0 += e10 + e11;
        s1 += e12 + e13;
        pa[kc][0] = pk2(e01, e00);
        pa[kc][1] = pk2(e03, e02);
        pa[kc][2] = pk2(e11, e10);
        pa[kc][3] = pk2(e13, e12);
    }
    s0 += __shfl_xor_sync(0xffffffffu, s0, 1);
    s0 += __shfl_xor_sync(0xffffffffu, s0, 2);
    s1 += __shfl_xor_sync(0xffffffffu, s1, 1);
    s1 += __shfl_xor_sync(0xffffffffu, s1, 2);
    const float r0i = 1.f / s0, r1i = 1.f / s1;

    cpa_wait0();                                  // v copy done
    __syncthreads();

    const uint32_t vAd = bt_addr(smem_u32(Qs), lane);
    bf16* od = g_o + base;
    const int row0 = wid * 16 + g;
#pragma unroll
    for (int hf = 0; hf < 2; ++hf) {              // O = P v (n-halves)
        float acc2[8][4];
#pragma unroll
        for (int n = 0; n < 8; ++n)
#pragma unroll
            for (int j = 0; j < 4; ++j) acc2[n][j] = 0.f;
#pragma unroll
        for (int kc = 0; kc < 8; ++kc) {
#pragma unroll
            for (int ng = 0; ng < 4; ++ng) {
                uint32_t bb[4];
                ldsm4t(bb, vAd + (uint32_t)(kc * 16) * 272u
                           + (uint32_t)((hf * 4 + ng) * 32));
                mma16816(acc2[2 * ng],     pa[kc], bb[0], bb[1]);
                mma16816(acc2[2 * ng + 1], pa[kc], bb[2], bb[3]);
            }
        }
#pragma unroll
        for (int nt = 0; nt < 8; ++nt) {
            int w = hf * 64 + 8 * nt + 2 * t;
            *(uint32_t*)(od + row0 * 128 + w)       = pk2(acc2[nt][1] * r0i, acc2[nt][0] * r0i);
            *(uint32_t*)(od + (row0 + 8) * 128 + w) = pk2(acc2[nt][3] * r1i, acc2[nt][2] * r1i);
        }
    }
}

// ---------------- epilogue (512 threads, split-group staging — R14) ----------------
#define EP_PARAM 69632
__global__ __launch_bounds__(512, 2)
void epi_kernel(const float* __restrict__ x1, const float* __restrict__ x2,
                const bf16* __restrict__ Wt, const float* __restrict__ bsv,
                const float* __restrict__ gamma, const float* __restrict__ beta,
                const float* __restrict__ mu, const float* __restrict__ var,
                float* __restrict__ out)
{
    extern __shared__ char sm[];
    uint32_t* As = (uint32_t*)sm;                 // o[c][w] (k-major A)
    uint32_t* Bs = As + 128 * SRU;                // Wt[d][k]
    float*    pA = (float*)(sm + EP_PARAM);
    float*    pB = pA + 128;
    float*    pC = pB + 128;
    const int tid = threadIdx.x;
    const int b = blockIdx.x >> 7, h = blockIdx.x & 127;

    const char* osrc = (const char*)(g_o + (size_t)b * CHWn + h * 128);
    const char* wsrc = (const char*)Wt;
    const uint32_t ad = smem_u32(As), bd = smem_u32(Bs);
#pragma unroll
    for (int i = 0; i < 2; ++i) {                 // group 1: k-half 0
        int idx = i * 512 + tid;
        int c = idx >> 4, q = idx & 15;
        cpa16(ad + (uint32_t)c * 272u + (uint32_t)(q * 16),
              osrc + (size_t)c * (HWn * 2) + q * 16);
        int d = idx >> 3, q2 = idx & 7;
        cpa16(bd + (uint32_t)d * 272u + (uint32_t)(q2 * 16), wsrc + d * 256 + q2 * 16);
    }
    cpa_commit();
#pragma unroll
    for (int i = 0; i < 2; ++i) {                 // group 2: k-half 1
        int idx = i * 512 + tid;
        int c = (idx >> 4) + 64, q = idx & 15;
        cpa16(ad + (uint32_t)c * 272u + (uint32_t)(q * 16),
              osrc + (size_t)c * (HWn * 2) + q * 16);
        int d = idx >> 3, q2 = (idx & 7) + 8;
        cpa16(bd + (uint32_t)d * 272u + (uint32_t)(q2 * 16), wsrc + d * 256 + q2 * 16);
    }
    cpa_commit();

    if (tid < 128) {
        float inv = rsqrtf(var[tid] + 1e-3f);
        pA[tid] = gamma[tid] * inv;
        pB[tid] = beta[tid] - gamma[tid] * mu[tid] * inv;
        pC[tid] = bsv[tid];
    }
    cpa_wait1();
    __syncthreads();

    const int wid = tid >> 5, lane = tid & 31;
    const int ws = wid >> 1, dh = wid & 1;
    const int g = lane >> 2, t = lane & 3;
    const uint32_t aAd = at_addr(smem_u32(As), ws * 16, lane);
    const uint32_t bAd = b_addr(smem_u32(Bs), lane);
    float acc[8][4];
#pragma unroll
    for (int n = 0; n < 8; ++n)
#pragma unroll
        for (int j = 0; j < 4; ++j) acc[n][j] = 0.f;
#pragma unroll
    for (int kc = 0; kc < 4; ++kc) {
        uint32_t a[4];
        ldsm4t(a, aAd + (uint32_t)(kc * 16) * 272u);
#pragma unroll
        for (int ng = 0; ng < 4; ++ng) {
            uint32_t bb[4];
            ldsm4(bb, bAd + (uint32_t)((dh * 4 + ng) * 16) * 272u + kc * 32);
            mma16816(acc[2 * ng],     a, bb[0], bb[1]);
            mma16816(acc[2 * ng + 1], a, bb[2], bb[3]);
        }
    }
    cpa_wait0();
    __syncthreads();
#pragma unroll
    for (int kc = 4; kc < 8; ++kc) {
        uint32_t a[4];
        ldsm4t(a, aAd + (uint32_t)(kc * 16) * 272u);
#pragma unroll
        for (int ng = 0; ng < 4; ++ng) {
            uint32_t bb[4];
            ldsm4(bb, bAd + (uint32_t)((dh * 4 + ng) * 16) * 272u + kc * 32);
            mma16816(acc[2 * ng],     a, bb[0], bb[1]);
            mma16816(acc[2 * ng + 1], a, bb[2], bb[3]);
        }
    }
    __syncthreads();                              // As/Bs dead; reuse as bounce

    float* Ob = (float*)sm + wid * (16 * EPW);
#pragma unroll
    for (int nt = 0; nt < 8; ++nt) {
        int ld = 8 * nt + 2 * t;
        Ob[g * EPW + ld]           = acc[nt][0];
        Ob[g * EPW + ld + 1]       = acc[nt][1];
        Ob[(g + 8) * EPW + ld]     = acc[nt][2];
        Ob[(g + 8) * EPW + ld + 1] = acc[nt][3];
    }
    __syncwarp();

    const size_t pbase = (size_t)(b * HWn + h * 128) * 128;
#pragma unroll
    for (int it = 0; it < 8; ++it) {
        int r2 = it * 2 + (lane >> 4);
        int cq = lane & 15;
        int w = ws * 16 + r2;
        int d = dh * 64 + cq * 4;
        size_t a = pbase + (size_t)w * 128 + d;
        float4 xa = *(const float4*)(x1 + a);
        float4 xb = *(const float4*)(x2 + a);
        float r[4];
#pragma unroll
        for (int j = 0; j < 4; ++j) {
            float z = Ob[r2 * EPW + cq * 4 + j] + pC[d + j];
            float s = 1.f / (1.f + __expf(-z));
            r[j] = pA[d + j] * s + pB[d + j];
        }
        *(float4*)(out + a) = make_float4(xa.x + xb.x * r[0], xa.y + xb.y * r[1],
                                          xa.z + xb.z * r[2], xa.w + xb.w * r[3]);
    }
}

// ---------------------------------------------------------------------------
extern "C" void kernel_launch(void* const* d_in, const int* in_sizes, int n_in,
                              void* d_out, int out_size)
{
    const float* x1    = (const float*)d_in[0];
    const float* x2    = (const float*)d_in[1];
    const float* Wq    = (const float*)d_in[2];
    const float* Wk    = (const float*)d_in[3];
    const float* Wv    = (const float*)d_in[4];
    const float* Ws    = (const float*)d_in[5];
    const float* bs    = (const float*)d_in[6];
    const float* scale = (const float*)d_in[7];
    const float* gamma = (const float*)d_in[8];
    const float* beta  = (const float*)d_in[9];
    const float* mu    = (const float*)d_in[10];
    const float* var   = (const float*)d_in[11];
    float* out = (float*)d_out;

    bf16* wt;
    cudaGetSymbolAddress((void**)&wt, g_Wt);

    const int sm_prep = 128 * 129 * 4;            // 66048
    const int sm_proj = 2 * TILE_B;               // 69632
    const int sm_attn = 2 * TILE_B;               // 69632 -> 3 CTAs/SM
    const int sm_epi  = EP_PARAM + 3 * 128 * 4;   // 71168
    cudaFuncSetAttribute(prep_w,      cudaFuncAttributeMaxDynamicSharedMemorySize, sm_prep);
    cudaFuncSetAttribute(proj_kernel, cudaFuncAttributeMaxDynamicSharedMemorySize, sm_proj);
    cudaFuncSetAttribute(attn_kernel, cudaFuncAttributeMaxDynamicSharedMemorySize, sm_attn);
    cudaFuncSetAttribute(epi_kernel,  cudaFuncAttributeMaxDynamicSharedMemorySize, sm_epi);

    dummy_k<<<1, 32>>>();                         // keep ncu capture on proj
    dummy_k<<<1, 32>>>();
    prep_w<<<4, 256, sm_prep>>>(Wq, Wk, Wv, Ws);
    proj_kernel<<<3072, 256, sm_proj>>>(x1, x2, wt);
    attn_kernel<<<1024, 256, sm_attn>>>(scale);
    epi_kernel<<<1024, 512, sm_epi>>>(x1, x2, wt + 3 * 16384, bs, gamma, beta, mu, var, out);
}

// round 17
// speedup vs baseline: 1.0981x; 1.0040x over previous
#include <cuda_runtime.h>
#include <cuda_bf16.h>
#include <cstdint>

typedef __nv_bfloat16 bf16;
#define HWn 16384
#define CHWn 2097152
#define TOTALn 16777216
#define SRU 68               // smem tile row stride in u32 (136 bf16, 272B)
#define TILE_B (128 * SRU * 4)   // 34816 bytes per bf16 tile
#define BPAD 136             // bf16 bounce row stride
#define EPW 68               // epi per-warp f32 bounce row stride

__device__ bf16 g_q[TOTALn];
__device__ bf16 g_k[TOTALn];
__device__ bf16 g_v[TOTALn];
__device__ bf16 g_o[TOTALn];
__device__ bf16 g_Wt[4 * 16384];   // transposed weights, [d][k] bf16

// ---------------- helpers ----------------
__device__ __forceinline__ uint32_t smem_u32(const void* p) {
    uint32_t a;
    asm("{ .reg .u64 t; cvta.to.shared.u64 t, %1; cvt.u32.u64 %0, t; }" : "=r"(a) : "l"(p));
    return a;
}
__device__ __forceinline__ uint32_t pk2(float hi, float lo) {
    uint32_t r;
    asm("cvt.rn.bf16x2.f32 %0, %1, %2;" : "=r"(r) : "f"(hi), "f"(lo));
    return r;
}
__device__ __forceinline__ void cpa16(uint32_t dst, const void* src) {
    asm volatile("cp.async.cg.shared.global [%0], [%1], 16;"
        :: "r"(dst), "l"(src) : "memory");
}
__device__ __forceinline__ void cpa_commit() {
    asm volatile("cp.async.commit_group;" ::: "memory");
}
__device__ __forceinline__ void cpa_wait0() {
    asm volatile("cp.async.wait_group 0;" ::: "memory");
}
__device__ __forceinline__ void cpa_wait1() {
    asm volatile("cp.async.wait_group 1;" ::: "memory");
}
__device__ __forceinline__ void ldsm4(uint32_t r[4], uint32_t addr) {
    asm volatile("ldmatrix.sync.aligned.m8n8.x4.shared.b16 {%0,%1,%2,%3}, [%4];"
        : "=r"(r[0]), "=r"(r[1]), "=r"(r[2]), "=r"(r[3]) : "r"(addr));
}
__device__ __forceinline__ void ldsm4t(uint32_t r[4], uint32_t addr) {
    asm volatile("ldmatrix.sync.aligned.m8n8.x4.trans.shared.b16 {%0,%1,%2,%3}, [%4];"
        : "=r"(r[0]), "=r"(r[1]), "=r"(r[2]), "=r"(r[3]) : "r"(addr));
}
__device__ __forceinline__ void mma16816(float c[4], const uint32_t a[4],
                                         uint32_t b0, uint32_t b1) {
    asm volatile("mma.sync.aligned.m16n8k16.row.col.f32.bf16.bf16.f32 "
        "{%0,%1,%2,%3},{%4,%5,%6,%7},{%8,%9},{%0,%1,%2,%3};"
        : "+f"(c[0]), "+f"(c[1]), "+f"(c[2]), "+f"(c[3])
        : "r"(a[0]), "r"(a[1]), "r"(a[2]), "r"(a[3]), "r"(b0), "r"(b1));
}

// ldmatrix address helpers (272B rows)
__device__ __forceinline__ uint32_t a_addr(uint32_t base, int mbase, int lane) {
    return base + (uint32_t)(mbase + (lane & 15)) * 272u + (uint32_t)((lane >> 4) << 4);
}
__device__ __forceinline__ uint32_t b_addr(uint32_t base, int lane) {
    int bn = (lane & 7) + (((lane >> 4) & 1) << 3);
    int bk = ((lane >> 3) & 1) << 4;
    return base + (uint32_t)bn * 272u + (uint32_t)bk;
}
__device__ __forceinline__ uint32_t bt_addr(uint32_t base, int lane) {
    int kr = (lane & 7) + (((lane >> 3) & 1) << 3);
    int nc = ((lane >> 4) & 1) << 3;
    return base + (uint32_t)kr * 272u + (uint32_t)(nc << 1);
}
__device__ __forceinline__ uint32_t at_addr(uint32_t base, int mbase, int lane) {
    int kr = (lane & 7) + (((lane >> 4) & 1) << 3);
    int mc = mbase + (((lane >> 3) & 1) << 3);
    return base + (uint32_t)kr * 272u + (uint32_t)(mc << 1);
}

// 32x64 warp-tile GEMM core (A non-trans, 2 m-tiles), n cols dh*64..+63
__device__ __forceinline__ void gemm32x64(float acc[2][8][4], uint32_t aAd,
                                          uint32_t bAd, int dh) {
#pragma unroll
    for (int mt = 0; mt < 2; ++mt)
#pragma unroll
        for (int n = 0; n < 8; ++n)
#pragma unroll
            for (int j = 0; j < 4; ++j) acc[mt][n][j] = 0.f;
#pragma unroll
    for (int kc = 0; kc < 8; ++kc) {
        uint32_t a0[4], a1[4];
        ldsm4(a0, aAd + kc * 32);
        ldsm4(a1, aAd + 16 * 272 + kc * 32);
#pragma unroll
        for (int ng = 0; ng < 4; ++ng) {
            uint32_t bb[4];
            ldsm4(bb, bAd + (uint32_t)((dh * 4 + ng) * 16) * 272u + kc * 32);
            mma16816(acc[0][2 * ng],     a0, bb[0], bb[1]);
            mma16816(acc[0][2 * ng + 1], a0, bb[2], bb[3]);
            mma16816(acc[1][2 * ng],     a1, bb[0], bb[1]);
            mma16816(acc[1][2 * ng + 1], a1, bb[2], bb[3]);
        }
    }
}

// profiler-steering dummy (1 -> capture window lands on attn)
__global__ void dummy_k() {}

// ---------------- prep: W[k][d] f32 -> Wt[d][k] bf16 ----------------
__global__ void prep_w(const float* __restrict__ W0, const float* __restrict__ W1,
                       const float* __restrict__ W2, const float* __restrict__ W3)
{
    extern __shared__ float wsm[];                      // [128][129]
    const float* src = blockIdx.x == 0 ? W0 : blockIdx.x == 1 ? W1
                     : blockIdx.x == 2 ? W2 : W3;
    for (int i = threadIdx.x; i < 16384; i += 256) wsm[(i >> 7) * 129 + (i & 127)] = src[i];
    __syncthreads();
    uint32_t* dst = (uint32_t*)(g_Wt + blockIdx.x * 16384);
    for (int i = threadIdx.x; i < 8192; i += 256) {
        int d = i >> 6, kk = i & 63;
        dst[d * 64 + kk] = pk2(wsm[(2 * kk + 1) * 129 + d], wsm[2 * kk * 129 + d]);
    }
}

// ---------------- projection: 256 thr, 8 warps of 32x64 tiles (R16) ----------------
__global__ __launch_bounds__(256, 2)
void proj_kernel(const float* __restrict__ x1, const float* __restrict__ x2,
                 const bf16* __restrict__ Wt)
{
    extern __shared__ char sm[];
    uint32_t* As = (uint32_t*)sm;                 // A[w][k]
    uint32_t* Ws = As + 128 * SRU;                // W tile [d][k]; becomes bounce
    bf16*     Bb = (bf16*)Ws;                     // bounce [c][w]
    const int tid = threadIdx.x;
    const int job = blockIdx.x;
    const bool isv = job >= 2048;
    const int typ = isv ? 2 : (job & 1);
    const int bh  = isv ? (job - 2048) : (job >> 1);
    const int b = bh >> 7, h = bh & 127;

    {
        const char* wsrc = (const char*)(Wt + typ * 16384);
        const uint32_t wd = smem_u32(Ws);
#pragma unroll
        for (int i = 0; i < 8; ++i) {
            int idx = i * 256 + tid;
            int d = idx >> 4, q = idx & 15;
            cpa16(wd + (uint32_t)d * 272u + (uint32_t)(q * 16), wsrc + idx * 16);
        }
        cpa_commit();
    }
    const float* src = (isv ? x2 : x1) + (size_t)(b * HWn + h * 128) * 128;
#pragma unroll
    for (int i = 0; i < 16; ++i) {
        int idx = i * 256 + tid;
        int w = idx >> 5, q = idx & 31;
        float4 f = *(const float4*)(src + w * 128 + q * 4);
        As[w * SRU + 2 * q]     = pk2(f.y, f.x);
        As[w * SRU + 2 * q + 1] = pk2(f.w, f.z);
    }
    cpa_wait0();
    __syncthreads();

    const int wid = tid >> 5, lane = tid & 31;
    const int ms = wid >> 1, dh = wid & 1;
    const int g = lane >> 2, t = lane & 3;
    const uint32_t aAd = a_addr(smem_u32(As), ms * 32, lane);
    const uint32_t bAd = b_addr(smem_u32(Ws), lane);
    bf16* dst = (typ == 0 ? g_q : typ == 1 ? g_k : g_v) + (size_t)b * CHWn + h * 128;

    float acc[2][8][4];
    gemm32x64(acc, aAd, bAd, dh);
    __syncthreads();                              // W reads done; Bb may overwrite

#pragma unroll
    for (int mt = 0; mt < 2; ++mt) {
        int r0 = ms * 32 + mt * 16 + g;
#pragma unroll
        for (int nt = 0; nt < 8; ++nt) {
            int c = dh * 64 + 8 * nt + 2 * t;
            Bb[c * BPAD + r0]           = __float2bfloat16(fmaxf(acc[mt][nt][0], 0.f));
            Bb[(c + 1) * BPAD + r0]     = __float2bfloat16(fmaxf(acc[mt][nt][1], 0.f));
            Bb[c * BPAD + r0 + 8]       = __float2bfloat16(fmaxf(acc[mt][nt][2], 0.f));
            Bb[(c + 1) * BPAD + r0 + 8] = __float2bfloat16(fmaxf(acc[mt][nt][3], 0.f));
        }
    }
    __syncthreads();
#pragma unroll
    for (int i = 0; i < 8; ++i) {
        int idx = i * 256 + tid;
        int c = idx >> 4, q = idx & 15;
        *(uint4*)(dst + (size_t)c * HWn + q * 8) = *(uint4*)(Bb + c * BPAD + q * 8);
    }
}

// ---------------- attention: 32x64 tiles, P through smem, cp.async v ----------------
#define AT_RED (2 * TILE_B)
__global__ __launch_bounds__(256, 2)
void attn_kernel(const float* __restrict__ scale_p)
{
    extern __shared__ char sm[];
    uint32_t* Qs = (uint32_t*)sm;                 // q[h][w]; later v[g][w]
    uint32_t* Ks = Qs + 128 * SRU;                // k[g][w]; later P[h][g] (bf16)
    float* red_max = (float*)(sm + AT_RED);       // [2][128]
    float* red_sum = red_max + 256;               // [2][128]
    const int tid = threadIdx.x;
    const size_t base = (size_t)blockIdx.x * HWn;
    const uint32_t qd = smem_u32(Qs), kd = smem_u32(Ks);

    {
        const char* qsrc = (const char*)(g_q + base);
        const char* ksrc = (const char*)(g_k + base);
#pragma unroll
        for (int i = 0; i < 8; ++i) {
            int idx = i * 256 + tid;
            uint32_t off = (uint32_t)(idx >> 4) * 272u + (uint32_t)((idx & 15) * 16);
            cpa16(qd + off, qsrc + idx * 16);
            cpa16(kd + off, ksrc + idx * 16);
        }
        cpa_commit();
        cpa_wait0();
    }
    __syncthreads();

    const int wid = tid >> 5, lane = tid & 31;
    const int ms = wid >> 1, dh = wid & 1;
    const int g = lane >> 2, t = lane & 3;
    const int r0 = ms * 32 + g;                   // mt0 row; mt1 = +16
    const float sc = scale_p[0];

    // S = q k^T (32x64 tile)
    float acc[2][8][4];
    gemm32x64(acc, a_addr(qd, ms * 32, lane), b_addr(kd, lane), dh);
    __syncthreads();                              // all S reads done (Qs, Ks free)

    {   // v -> Qs cp.asyncs; softmax below overlaps the copy
        const char* vsrc = (const char*)(g_v + base);
#pragma unroll
        for (int i = 0; i < 8; ++i) {
            int idx = i * 256 + tid;
            uint32_t off = (uint32_t)(idx >> 4) * 272u + (uint32_t)((idx & 15) * 16);
            cpa16(qd + off, vsrc + idx * 16);
        }
        cpa_commit();
    }

    // partial row max over this warp's 64 cols
    float mm[2][2] = {{-1e30f, -1e30f}, {-1e30f, -1e30f}};
#pragma unroll
    for (int mt = 0; mt < 2; ++mt)
#pragma unroll
        for (int nt = 0; nt < 8; ++nt) {
#pragma unroll
            for (int j = 0; j < 4; ++j) acc[mt][nt][j] *= sc;
            mm[mt][0] = fmaxf(mm[mt][0], fmaxf(acc[mt][nt][0], acc[mt][nt][1]));
            mm[mt][1] = fmaxf(mm[mt][1], fmaxf(acc[mt][nt][2], acc[mt][nt][3]));
        }
#pragma unroll
    for (int mt = 0; mt < 2; ++mt)
#pragma unroll
        for (int hh = 0; hh < 2; ++hh) {
            mm[mt][hh] = fmaxf(mm[mt][hh], __shfl_xor_sync(0xffffffffu, mm[mt][hh], 1));
            mm[mt][hh] = fmaxf(mm[mt][hh], __shfl_xor_sync(0xffffffffu, mm[mt][hh], 2));
        }
    if (t == 0) {
#pragma unroll
        for (int mt = 0; mt < 2; ++mt) {
            red_max[dh * 128 + r0 + mt * 16]     = mm[mt][0];
            red_max[dh * 128 + r0 + mt * 16 + 8] = mm[mt][1];
        }
    }
    __syncthreads();                              // max partials visible
#pragma unroll
    for (int mt = 0; mt < 2; ++mt) {
        mm[mt][0] = fmaxf(red_max[r0 + mt * 16],     red_max[128 + r0 + mt * 16]);
        mm[mt][1] = fmaxf(red_max[r0 + mt * 16 + 8], red_max[128 + r0 + mt * 16 + 8]);
    }

    // exp + partial sums + store unnormalized P (bf16) into Ks home
    float ss[2][2] = {{0.f, 0.f}, {0.f, 0.f}};
#pragma unroll
    for (int mt = 0; mt < 2; ++mt)
#pragma unroll
        for (int nt = 0; nt < 8; ++nt) {
            float e0 = __expf(acc[mt][nt][0] - mm[mt][0]);
            float e1 = __expf(acc[mt][nt][1] - mm[mt][0]);
            float e2 = __expf(acc[mt][nt][2] - mm[mt][1]);
            float e3 = __expf(acc[mt][nt][3] - mm[mt][1]);
            ss[mt][0] += e0 + e1;
            ss[mt][1] += e2 + e3;
            int cu = dh * 32 + 4 * nt + t;
            Ks[(r0 + mt * 16) * SRU + cu]     = pk2(e1, e0);
            Ks[(r0 + mt * 16 + 8) * SRU + cu] = pk2(e3, e2);
        }
#pragma unroll
    for (int mt = 0; mt < 2; ++mt)
#pragma unroll
        for (int hh = 0; hh < 2; ++hh) {
            ss[mt][hh] += __shfl_xor_sync(0xffffffffu, ss[mt][hh], 1);
            ss[mt][hh] += __shfl_xor_sync(0xffffffffu, ss[mt][hh], 2);
        }
    if (t == 0) {
#pragma unroll
        for (int mt = 0; mt < 2; ++mt) {
            red_sum[dh * 128 + r0 + mt * 16]     = ss[mt][0];
            red_sum[dh * 128 + r0 + mt * 16 + 8] = ss[mt][1];
        }
    }
    cpa_wait0();                                  // v landed in Qs
    __syncthreads();                              // P + sums + v visible

    float ri[2][2];
#pragma unroll
    for (int mt = 0; mt < 2; ++mt) {
        ri[mt][0] = 1.f / (red_sum[r0 + mt * 16]     + red_sum[128 + r0 + mt * 16]);
        ri[mt][1] = 1.f / (red_sum[r0 + mt * 16 + 8] + red_sum[128 + r0 + mt * 16 + 8]);
    }

    // O = P v : A = P (Ks, non-trans), B = v^T (Qs, trans), 32x64 tile
    const uint32_t pAd = a_addr(kd, ms * 32, lane);
    const uint32_t vAd = bt_addr(qd, lane) + (uint32_t)(dh * 128);
    float acc2[2][8][4];
#pragma unroll
    for (int mt = 0; mt < 2; ++mt)
#pragma unroll
        for (int n = 0; n < 8; ++n)
#pragma unroll
            for (int j = 0; j < 4; ++j) acc2[mt][n][j] = 0.f;
#pragma unroll
    for (int kc = 0; kc < 8; ++kc) {
        uint32_t a0[4], a1[4];
        ldsm4(a0, pAd + kc * 32);
        ldsm4(a1, pAd + 16 * 272 + kc * 32);
#pragma unroll
        for (int ng = 0; ng < 4; ++ng) {
            uint32_t bb[4];
            ldsm4t(bb, vAd + (uint32_t)(kc * 16) * 272u + (uint32_t)(ng * 32));
            mma16816(acc2[0][2 * ng],     a0, bb[0], bb[1]);
            mma16816(acc2[0][2 * ng + 1], a0, bb[2], bb[3]);
            mma16816(acc2[1][2 * ng],     a1, bb[0], bb[1]);
            mma16816(acc2[1][2 * ng + 1], a1, bb[2], bb[3]);
        }
    }

    bf16* od = g_o + base;
#pragma unroll
    for (int mt = 0; mt < 2; ++mt) {
        int r = r0 + mt * 16;
#pragma unroll
        for (int nt = 0; nt < 8; ++nt) {
            int w = dh * 64 + 8 * nt + 2 * t;
            *(uint32_t*)(od + r * 128 + w) =
                pk2(acc2[mt][nt][1] * ri[mt][0], acc2[mt][nt][0] * ri[mt][0]);
            *(uint32_t*)(od + (r + 8) * 128 + w) =
                pk2(acc2[mt][nt][3] * ri[mt][1], acc2[mt][nt][2] * ri[mt][1]);
        }
    }
}

// ---------------- epilogue (512 threads, split-group staging — R14) ----------------
#define EP_PARAM 69632
__global__ __launch_bounds__(512, 2)
void epi_kernel(const float* __restrict__ x1, const float* __restrict__ x2,
                const bf16* __restrict__ Wt, const float* __restrict__ bsv,
                const float* __restrict__ gamma, const float* __restrict__ beta,
                const float* __restrict__ mu, const float* __restrict__ var,
                float* __restrict__ out)
{
    extern __shared__ char sm[];
    uint32_t* As = (uint32_t*)sm;                 // o[c][w] (k-major A)
    uint32_t* Bs = As + 128 * SRU;                // Wt[d][k]
    float*    pA = (float*)(sm + EP_PARAM);
    float*    pB = pA + 128;
    float*    pC = pB + 128;
    const int tid = threadIdx.x;
    const int b = blockIdx.x >> 7, h = blockIdx.x & 127;

    const char* osrc = (const char*)(g_o + (size_t)b * CHWn + h * 128);
    const char* wsrc = (const char*)Wt;
    const uint32_t ad = smem_u32(As), bd = smem_u32(Bs);
#pragma unroll
    for (int i = 0; i < 2; ++i) {                 // group 1: k-half 0
        int idx = i * 512 + tid;
        int c = idx >> 4, q = idx & 15;
        cpa16(ad + (uint32_t)c * 272u + (uint32_t)(q * 16),
              osrc + (size_t)c * (HWn * 2) + q * 16);
        int d = idx >> 3, q2 = idx & 7;
        cpa16(bd + (uint32_t)d * 272u + (uint32_t)(q2 * 16), wsrc + d * 256 + q2 * 16);
    }
    cpa_commit();
#pragma unroll
    for (int i = 0; i < 2; ++i) {                 // group 2: k-half 1
        int idx = i * 512 + tid;
        int c = (idx >> 4) + 64, q = idx & 15;
        cpa16(ad + (uint32_t)c * 272u + (uint32_t)(q * 16),
              osrc + (size_t)c * (HWn * 2) + q * 16);
        int d = idx >> 3, q2 = (idx & 7) + 8;
        cpa16(bd + (uint32_t)d * 272u + (uint32_t)(q2 * 16), wsrc + d * 256 + q2 * 16);
    }
    cpa_commit();

    if (tid < 128) {
        float inv = rsqrtf(var[tid] + 1e-3f);
        pA[tid] = gamma[tid] * inv;
        pB[tid] = beta[tid] - gamma[tid] * mu[tid] * inv;
        pC[tid] = bsv[tid];
    }
    cpa_wait1();
    __syncthreads();

    const int wid = tid >> 5, lane = tid & 31;
    const int ws = wid >> 1, dh = wid & 1;
    const int g = lane >> 2, t = lane & 3;
    const uint32_t aAd = at_addr(smem_u32(As), ws * 16, lane);
    const uint32_t bAd = b_addr(smem_u32(Bs), lane);
    float acc[8][4];
#pragma unroll
    for (int n = 0; n < 8; ++n)
#pragma unroll
        for (int j = 0; j < 4; ++j) acc[n][j] = 0.f;
#pragma unroll
    for (int kc = 0; kc < 4; ++kc) {
        uint32_t a[4];
        ldsm4t(a, aAd + (uint32_t)(kc * 16) * 272u);
#pragma unroll
        for (int ng = 0; ng < 4; ++ng) {
            uint32_t bb[4];
            ldsm4(bb, bAd + (uint32_t)((dh * 4 + ng) * 16) * 272u + kc * 32);
            mma16816(acc[2 * ng],     a, bb[0], bb[1]);
            mma16816(acc[2 * ng + 1], a, bb[2], bb[3]);
        }
    }
    cpa_wait0();
    __syncthreads();
#pragma unroll
    for (int kc = 4; kc < 8; ++kc) {
        uint32_t a[4];
        ldsm4t(a, aAd + (uint32_t)(kc * 16) * 272u);
#pragma unroll
        for (int ng = 0; ng < 4; ++ng) {
            uint32_t bb[4];
            ldsm4(bb, bAd + (uint32_t)((dh * 4 + ng) * 16) * 272u + kc * 32);
            mma16816(acc[2 * ng],     a, bb[0], bb[1]);
            mma16816(acc[2 * ng + 1], a, bb[2], bb[3]);
        }
    }
    __syncthreads();                              // As/Bs dead; reuse as bounce

    float* Ob = (float*)sm + wid * (16 * EPW);
#pragma unroll
    for (int nt = 0; nt < 8; ++nt) {
        int ld = 8 * nt + 2 * t;
        Ob[g * EPW + ld]           = acc[nt][0];
        Ob[g * EPW + ld + 1]       = acc[nt][1];
        Ob[(g + 8) * EPW + ld]     = acc[nt][2];
        Ob[(g + 8) * EPW + ld + 1] = acc[nt][3];
    }
    __syncwarp();

    const size_t pbase = (size_t)(b * HWn + h * 128) * 128;
#pragma unroll
    for (int it = 0; it < 8; ++it) {
        int r2 = it * 2 + (lane >> 4);
        int cq = lane & 15;
        int w = ws * 16 + r2;
        int d = dh * 64 + cq * 4;
        size_t a = pbase + (size_t)w * 128 + d;
        float4 xa = *(const float4*)(x1 + a);
        float4 xb = *(const float4*)(x2 + a);
        float r[4];
#pragma unroll
        for (int j = 0; j < 4; ++j) {
            float z = Ob[r2 * EPW + cq * 4 + j] + pC[d + j];
            float s = 1.f / (1.f + __expf(-z));
            r[j] = pA[d + j] * s + pB[d + j];
        }
        *(float4*)(out + a) = make_float4(xa.x + xb.x * r[0], xa.y + xb.y * r[1],
                                          xa.z + xb.z * r[2], xa.w + xb.w * r[3]);
    }
}

// ---------------------------------------------------------------------------
extern "C" void kernel_launch(void* const* d_in, const int* in_sizes, int n_in,
                              void* d_out, int out_size)
{
    const float* x1    = (const float*)d_in[0];
    const float* x2    = (const float*)d_in[1];
    const float* Wq    = (const float*)d_in[2];
    const float* Wk    = (const float*)d_in[3];
    const float* Wv    = (const float*)d_in[4];
    const float* Ws    = (const float*)d_in[5];
    const float* bs    = (const float*)d_in[6];
    const float* scale = (const float*)d_in[7];
    const float* gamma = (const float*)d_in[8];
    const float* beta  = (const float*)d_in[9];
    const float* mu    = (const float*)d_in[10];
    const float* var   = (const float*)d_in[11];
    float* out = (float*)d_out;

    bf16* wt;
    cudaGetSymbolAddress((void**)&wt, g_Wt);

    const int sm_prep = 128 * 129 * 4;            // 66048
    const int sm_proj = 2 * TILE_B;               // 69632
    const int sm_attn = 2 * TILE_B + 2048;        // 71680
    const int sm_epi  = EP_PARAM + 3 * 128 * 4;   // 71168
    cudaFuncSetAttribute(prep_w,      cudaFuncAttributeMaxDynamicSharedMemorySize, sm_prep);
    cudaFuncSetAttribute(proj_kernel, cudaFuncAttributeMaxDynamicSharedMemorySize, sm_proj);
    cudaFuncSetAttribute(attn_kernel, cudaFuncAttributeMaxDynamicSharedMemorySize, sm_attn);
    cudaFuncSetAttribute(epi_kernel,  cudaFuncAttributeMaxDynamicSharedMemorySize, sm_epi);

    dummy_k<<<1, 32>>>();                         // steer ncu capture onto attn
    prep_w<<<4, 256, sm_prep>>>(Wq, Wk, Wv, Ws);
    proj_kernel<<<3072, 256, sm_proj>>>(x1, x2, wt);
    attn_kernel<<<1024, 256, sm_attn>>>(scale);
    epi_kernel<<<1024, 512, sm_epi>>>(x1, x2, wt + 3 * 16384, bs, gamma, beta, mu, var, out);
}